// round 16
// baseline (speedup 1.0000x reference)
#include <cuda_runtime.h>
#include <cuda_fp16.h>
#include <cstdint>

#define NB 4
#define NN 2048
#define NC 256
#define NH 4
#define HD 64

// ---- scratch (allocation-free) ----
__device__ __half g_nodeh[NB*NN*NC];
__device__ __half g_WT[3*NC*NC];               // transposed fp16 weights [n][k]
__device__ __half g_Xh[NB*NN*NC];
__device__ __half g_qh[NB*NN*NC];
__device__ __half g_kh[NB*NN*NC];
__device__ __half g_XT[NB*NH*HD*NN];           // [bh][d][y], dis_y folded
__device__ float  g_Y[NB*NN*NC];
__device__ float  g_dis[NB*NH*NN];
__device__ __half g_Wh[(size_t)NB*NH*NN*NN];   // 128MB fp16

__device__ __forceinline__ void mma_f16(float c[4], const uint32_t a[4], const uint32_t b[2]) {
    asm volatile(
        "mma.sync.aligned.m16n8k16.row.col.f32.f16.f16.f32 "
        "{%0,%1,%2,%3}, {%4,%5,%6,%7}, {%8,%9}, {%0,%1,%2,%3};"
        : "+f"(c[0]), "+f"(c[1]), "+f"(c[2]), "+f"(c[3])
        : "r"(a[0]), "r"(a[1]), "r"(a[2]), "r"(a[3]), "r"(b[0]), "r"(b[1]));
}
__device__ __forceinline__ uint32_t smem_cast(const void* p) {
    return (uint32_t)__cvta_generic_to_shared(p);
}
__device__ __forceinline__ void ldsm_x4(uint32_t& r0, uint32_t& r1, uint32_t& r2, uint32_t& r3,
                                        uint32_t addr) {
    asm volatile("ldmatrix.sync.aligned.m8n8.x4.shared.b16 {%0,%1,%2,%3}, [%4];"
        : "=r"(r0), "=r"(r1), "=r"(r2), "=r"(r3) : "r"(addr));
}
__device__ __forceinline__ void cp16(void* s, const void* g) {
    asm volatile("cp.async.cg.shared.global [%0], [%1], 16;"
        :: "r"(smem_cast(s)), "l"(g));
}
#define CP_COMMIT() asm volatile("cp.async.commit_group;" ::: "memory")

// a * sigmoid(s/8), accurate (~1e-6 rel)
__device__ __forceinline__ float sigw(float a, float s) {
    float e = __expf(-0.125f * s);
    return __fdividef(a, 1.f + e);
}

// ============================================================
// K0a: node fp32 -> fp16
// ============================================================
__global__ __launch_bounds__(256) void k0_node(const float* __restrict__ node) {
    int idx = (blockIdx.x * 256 + threadIdx.x) * 8;
    float4 v0 = *(const float4*)(node + idx);
    float4 v1 = *(const float4*)(node + idx + 4);
    __half2 h[4];
    h[0] = __float22half2_rn(make_float2(v0.x, v0.y));
    h[1] = __float22half2_rn(make_float2(v0.z, v0.w));
    h[2] = __float22half2_rn(make_float2(v1.x, v1.y));
    h[3] = __float22half2_rn(make_float2(v1.z, v1.w));
    *(uint4*)(g_nodeh + idx) = *(uint4*)h;
}

// ============================================================
// K0b: weights fp32 [k][n] -> fp16 transposed [n][k]
// ============================================================
__global__ __launch_bounds__(256) void k0_wt(const float* __restrict__ W0,
                                             const float* __restrict__ W1,
                                             const float* __restrict__ W2) {
    __shared__ __half T[64*72];
    const int tid = threadIdx.x;
    const int k0 = blockIdx.x * 64, n0 = blockIdx.y * 64, z = blockIdx.z;
    const float* src = (z == 0) ? W0 : ((z == 1) ? W1 : W2);
    {
        int r = tid >> 2, cp = tid & 3;
        const float* s = src + (size_t)(k0 + r)*NC + n0 + cp*16;
        __half* d = T + r*72 + cp*16;
        #pragma unroll
        for (int u = 0; u < 4; u++) {
            float4 v = *(const float4*)(s + u*4);
            ((__half2*)d)[u*2]   = __float22half2_rn(make_float2(v.x, v.y));
            ((__half2*)d)[u*2+1] = __float22half2_rn(make_float2(v.z, v.w));
        }
    }
    __syncthreads();
    {
        int r = tid >> 2, cp = tid & 3;
        __half* dst = g_WT + (size_t)z*NC*NC + (size_t)(n0 + r)*NC + k0 + cp*16;
        __half tmp[16];
        #pragma unroll
        for (int u = 0; u < 16; u++)
            tmp[u] = T[(cp*16 + u)*72 + r];
        *(uint4*)(dst)     = *(uint4*)(tmp);
        *(uint4*)(dst + 8) = *(uint4*)(tmp + 8);
    }
}

// ============================================================
// K1 (mma fp16): out = lrelu(node @ W (+bias)), z selects W
// ============================================================
__global__ __launch_bounds__(256) void k1_f16(const float* __restrict__ bias) {
    __shared__ __half As[128*72];
    __shared__ __half Bs[128*72];
    const int tid = threadIdx.x;
    const int wid = tid >> 5, lid = tid & 31;
    const int grp = lid >> 2, tg = lid & 3;
    const int wm = wid >> 2, wn = wid & 3;
    const int z = blockIdx.z;
    const int M0 = blockIdx.y * 128, N0 = blockIdx.x * 128;
    __half* outp = (z == 0) ? g_Xh : ((z == 1) ? g_qh : g_kh);
    const __half* Asrc = g_nodeh + (size_t)M0*NC;
    const __half* Bsrc = g_WT + (size_t)z*NC*NC + (size_t)N0*NC;
    const int srow = tid >> 1, spart = tid & 1;
    const int a_row = lid & 15, a_koff = (lid >> 4) * 8;
    const int b_row = ((lid >> 4) & 1) * 8 + (lid & 7), b_koff = ((lid >> 3) & 1) * 8;

    float acc[4][4][4] = {};
    for (int kc = 0; kc < 4; kc++) {
        const int k0 = kc * 64;
        __syncthreads();
        {
            const uint4* g = (const uint4*)(Asrc + (size_t)srow*NC + k0 + spart*32);
            uint4* s = (uint4*)(As + srow*72 + spart*32);
            s[0]=g[0]; s[1]=g[1]; s[2]=g[2]; s[3]=g[3];
            const uint4* gb = (const uint4*)(Bsrc + (size_t)srow*NC + k0 + spart*32);
            uint4* sb = (uint4*)(Bs + srow*72 + spart*32);
            sb[0]=gb[0]; sb[1]=gb[1]; sb[2]=gb[2]; sb[3]=gb[3];
        }
        __syncthreads();
        #pragma unroll
        for (int kk = 0; kk < 4; kk++) {
            uint32_t a[4][4], bf[4][2];
            #pragma unroll
            for (int i = 0; i < 4; i++) {
                uint32_t ad = smem_cast(As + (wm*64 + i*16 + a_row)*72 + kk*16 + a_koff);
                ldsm_x4(a[i][0], a[i][1], a[i][2], a[i][3], ad);
            }
            #pragma unroll
            for (int jj = 0; jj < 2; jj++) {
                uint32_t bd = smem_cast(Bs + (wn*32 + jj*16 + b_row)*72 + kk*16 + b_koff);
                ldsm_x4(bf[2*jj][0], bf[2*jj][1], bf[2*jj+1][0], bf[2*jj+1][1], bd);
            }
            #pragma unroll
            for (int i = 0; i < 4; i++)
                #pragma unroll
                for (int j = 0; j < 4; j++)
                    mma_f16(acc[i][j], a[i], bf[j]);
        }
    }
    #pragma unroll
    for (int i = 0; i < 4; i++)
        #pragma unroll
        for (int u = 0; u < 2; u++) {
            int row = M0 + wm*64 + i*16 + grp + u*8;
            #pragma unroll
            for (int j = 0; j < 4; j++) {
                int col = N0 + wn*32 + j*8 + tg*2;
                float v0 = acc[i][j][u*2], v1 = acc[i][j][u*2+1];
                if (z == 0) { v0 += bias[col]; v1 += bias[col+1]; }
                v0 = (v0 >= 0.f) ? v0 : 0.01f*v0;
                v1 = (v1 >= 0.f) ? v1 : 0.01f*v1;
                *(__half2*)(outp + (size_t)row*NC + col) =
                    __float22half2_rn(make_float2(v0, v1));
            }
        }
}

// ============================================================
// K2 (mma fp16, 128x64 y-tiles, 3 CTAs/SM):
// W = adj*sigmoid(q.k/8) -> fp16, dis = rsqrt(rowsum)
// 8 warps: wm=wid>>1 (4 x 32 rows), wn=wid&1 (2 x 32 cols)
// ============================================================
__global__ __launch_bounds__(256, 3) void k2_att_mma(const float* __restrict__ adj) {
    extern __shared__ char smraw[];
    __half* qs  = (__half*)smraw;                 // 128*72 halves (18432B)
    __half* ks  = qs + 128*72;                    // 64*72 halves  (9216B)
    __half* Sh  = ks + 64*72;                     // 128*72 halves (18432B)
    float*  red = (float*)(Sh + 128*72);          // 128 floats (512B)
    const int tid = threadIdx.x;
    const int wid = tid >> 5, lid = tid & 31;
    const int grp = lid >> 2, tg = lid & 3;
    const int wm = wid >> 1, wn = wid & 1;
    const int bh = blockIdx.y;
    const int b = bh >> 2, h = bh & 3;
    const int x0 = blockIdx.x * 128;
    const int qrow = tid >> 1, qpart = tid & 1;
    const int krow = tid >> 2, kpart = tid & 3;
    const int rl8 = lid >> 3, rl = lid & 7;

    const int a_row = lid & 15, a_koff = (lid >> 4) * 8;
    const int b_row = ((lid >> 4) & 1) * 8 + (lid & 7), b_koff = ((lid >> 3) & 1) * 8;

    {   // stage q once: 128 rows x 64 halves
        const uint4* g = (const uint4*)(g_qh + ((size_t)(b*NN + x0 + qrow))*NC + h*HD + qpart*32);
        uint4* s = (uint4*)(qs + qrow*72 + qpart*32);
        s[0]=g[0]; s[1]=g[1]; s[2]=g[2]; s[3]=g[3];
    }
    if (tid < 128) red[tid] = 0.f;

    const __half* ksrc  = g_kh + (size_t)b*NN*NC + h*HD;
    const float*  abase = adj + (size_t)b*NN*NN;
    __half* wbase = g_Wh + (size_t)bh*NN*NN;

    for (int yt = 0; yt < NN/64; yt++) {
        const int y0 = yt * 64;
        {   // stage k tile: 64 rows x 64 halves (4 thr/row x 16 halves)
            const uint4* g = (const uint4*)(ksrc + (size_t)(y0 + krow)*NC + kpart*16);
            uint4* s = (uint4*)(ks + krow*72 + kpart*16);
            s[0]=g[0]; s[1]=g[1];
        }
        __syncthreads();
        float acc[2][4][4] = {};
        #pragma unroll
        for (int kk = 0; kk < 4; kk++) {
            uint32_t a[2][4], bf[4][2];
            #pragma unroll
            for (int i = 0; i < 2; i++) {
                uint32_t ad = smem_cast(qs + (wm*32 + i*16 + a_row)*72 + kk*16 + a_koff);
                ldsm_x4(a[i][0], a[i][1], a[i][2], a[i][3], ad);
            }
            #pragma unroll
            for (int jj = 0; jj < 2; jj++) {
                uint32_t bd = smem_cast(ks + (wn*32 + jj*16 + b_row)*72 + kk*16 + b_koff);
                ldsm_x4(bf[2*jj][0], bf[2*jj][1], bf[2*jj+1][0], bf[2*jj+1][1], bd);
            }
            #pragma unroll
            for (int i = 0; i < 2; i++)
                #pragma unroll
                for (int j = 0; j < 4; j++)
                    mma_f16(acc[i][j], a[i], bf[j]);
        }
        // dump S frags to smem as fp16
        #pragma unroll
        for (int i = 0; i < 2; i++) {
            int xr = wm*32 + i*16 + grp;
            #pragma unroll
            for (int j = 0; j < 4; j++) {
                int col = wn*32 + j*8 + 2*tg;
                *(__half2*)(Sh + xr*72 + col) =
                    __float22half2_rn(make_float2(acc[i][j][0], acc[i][j][1]));
                *(__half2*)(Sh + (xr+8)*72 + col) =
                    __float22half2_rn(make_float2(acc[i][j][2], acc[i][j][3]));
            }
        }
        __syncthreads();
        // coalesced epilogue, hoisted loads
        #pragma unroll
        for (int p = 0; p < 4; p++) {
            int xr = p*32 + wid*4 + rl8;
            const __half* Srow = Sh + xr*72;
            const float* arow = abase + (size_t)(x0 + xr)*NN + y0;
            __half* wrow = wbase + (size_t)(x0 + xr)*NN + y0;
            float4 av[2];
            uint2 svh[2];
            #pragma unroll
            for (int c = 0; c < 2; c++) av[c] = *(const float4*)(arow + c*32 + rl*4);
            #pragma unroll
            for (int c = 0; c < 2; c++) svh[c] = *(const uint2*)(Srow + c*32 + rl*4);
            float lsum = 0.f;
            #pragma unroll
            for (int c = 0; c < 2; c++) {
                float2 s01 = __half22float2(*(__half2*)&svh[c].x);
                float2 s23 = __half22float2(*(__half2*)&svh[c].y);
                float w0 = sigw(av[c].x, s01.x);
                float w1 = sigw(av[c].y, s01.y);
                float w2 = sigw(av[c].z, s23.x);
                float w3 = sigw(av[c].w, s23.y);
                __half2 h0 = __float22half2_rn(make_float2(w0, w1));
                __half2 h1 = __float22half2_rn(make_float2(w2, w3));
                uint2 st = make_uint2(*(uint32_t*)&h0, *(uint32_t*)&h1);
                *(uint2*)(wrow + c*32 + rl*4) = st;
                lsum += (w0 + w1) + (w2 + w3);
            }
            lsum += __shfl_xor_sync(0xffffffffu, lsum, 1);
            lsum += __shfl_xor_sync(0xffffffffu, lsum, 2);
            lsum += __shfl_xor_sync(0xffffffffu, lsum, 4);
            if (rl == 0) red[xr] += lsum;
        }
        __syncthreads();
    }
    if (tid < 128) {
        float v = red[tid];
        g_dis[bh*NN + x0 + tid] = (v > 0.f) ? rsqrtf(v) : 0.f;
    }
}

// ============================================================
// K3x: g_XT[bh][d][y] = fp16(dis_y * X[b,y,h*64+d])
// ============================================================
__global__ __launch_bounds__(256) void k3_xt() {
    __shared__ __half T[64*72];
    const int tid = threadIdx.x;
    const int yt = blockIdx.x, bh = blockIdx.y;
    const int b = bh >> 2, h = bh & 3;
    const int y0 = yt * 64;
    {
        int yr = tid >> 2, cp = tid & 3;
        float dy = g_dis[bh*NN + y0 + yr];
        const __half* src = g_Xh + ((size_t)(b*NN + y0 + yr))*NC + h*HD + cp*16;
        __half* dst = T + yr*72 + cp*16;
        #pragma unroll
        for (int u = 0; u < 8; u++) {
            float2 f = __half22float2(((const __half2*)src)[u]);
            ((__half2*)dst)[u] = __float22half2_rn(make_float2(f.x*dy, f.y*dy));
        }
    }
    __syncthreads();
    {
        int dr = tid >> 2, cp = tid & 3;
        __half* dst = g_XT + ((size_t)bh*HD + dr)*NN + y0 + cp*16;
        __half tmp[16];
        #pragma unroll
        for (int u = 0; u < 16; u++)
            tmp[u] = T[(cp*16 + u)*72 + dr];
        *(uint4*)(dst)     = *(uint4*)(tmp);
        *(uint4*)(dst + 8) = *(uint4*)(tmp + 8);
    }
}

// ============================================================
// K4 (mma fp16, 64x64 tile, grid 512, 3-stage cp.async, 1 sync/iter)
// ============================================================
#define K4_ITERS (NN/64)
__global__ __launch_bounds__(256, 4) void k4_agg_mma() {
    extern __shared__ char smraw[];
    __half* Ws = (__half*)smraw;          // 3 x 64*72
    __half* Xs = Ws + 3*64*72;            // 3 x 64*72
    const int tid = threadIdx.x;
    const int wid = tid >> 5, lid = tid & 31;
    const int grp = lid >> 2, tg = lid & 3;
    const int wm = wid >> 2, wn = wid & 3;
    const int bh = blockIdx.y;
    const int b = bh >> 2, h = bh & 3;
    const int x0 = blockIdx.x * 64;
    const __half* wsrc  = g_Wh + (size_t)bh*NN*NN + (size_t)x0*NN;
    const __half* xtsrc = g_XT + (size_t)bh*HD*NN;
    const float*  disb  = g_dis + bh*NN;
    const int row4 = tid >> 2, part4 = tid & 3;
    const int a_row = lid & 15, a_koff = (lid >> 4) * 8;
    const int b_row = ((lid >> 4) & 1) * 8 + (lid & 7), b_koff = ((lid >> 3) & 1) * 8;

    auto issue = [&](int it) {
        int st = it % 3;
        int y0 = it * 64;
        const __half* gw = wsrc + (size_t)row4*NN + y0 + part4*16;
        __half* sw = Ws + st*64*72 + row4*72 + part4*16;
        cp16(sw, gw); cp16(sw + 8, gw + 8);
        const __half* gx = xtsrc + (size_t)row4*NN + y0 + part4*16;
        __half* sx = Xs + st*64*72 + row4*72 + part4*16;
        cp16(sx, gx); cp16(sx + 8, gx + 8);
        CP_COMMIT();
    };

    issue(0);
    issue(1);
    float acc[2][2][4] = {};
    for (int it = 0; it < K4_ITERS; it++) {
        if (it + 1 < K4_ITERS) {
            asm volatile("cp.async.wait_group 1;" ::: "memory");
        } else {
            asm volatile("cp.async.wait_group 0;" ::: "memory");
        }
        __syncthreads();
        if (it + 2 < K4_ITERS) issue(it + 2);
        __half* Wb = Ws + (it % 3) * 64*72;
        __half* Xb = Xs + (it % 3) * 64*72;
        #pragma unroll
        for (int kk = 0; kk < 4; kk++) {
            uint32_t a[2][4], bf[2][2];
            #pragma unroll
            for (int i = 0; i < 2; i++) {
                uint32_t ad = smem_cast(Wb + (wm*32 + i*16 + a_row)*72 + kk*16 + a_koff);
                ldsm_x4(a[i][0], a[i][1], a[i][2], a[i][3], ad);
            }
            {
                uint32_t bd = smem_cast(Xb + (wn*16 + b_row)*72 + kk*16 + b_koff);
                ldsm_x4(bf[0][0], bf[0][1], bf[1][0], bf[1][1], bd);
            }
            #pragma unroll
            for (int i = 0; i < 2; i++)
                #pragma unroll
                for (int j = 0; j < 2; j++)
                    mma_f16(acc[i][j], a[i], bf[j]);
        }
    }
    #pragma unroll
    for (int i = 0; i < 2; i++) {
        #pragma unroll
        for (int u = 0; u < 2; u++) {
            int x = x0 + wm*32 + i*16 + grp + u*8;
            float dx = disb[x];
            float* dst = g_Y + (size_t)(b*NN + x)*NC + h*HD + wn*16 + tg*2;
            #pragma unroll
            for (int j = 0; j < 2; j++)
                *(float2*)(dst + j*8) = make_float2(acc[i][j][u*2]*dx, acc[i][j][u*2+1]*dx);
        }
    }
}

// ============================================================
// K5: LayerNorm over last dim (256), warp per row
// ============================================================
__global__ __launch_bounds__(256) void k5_ln(const float* __restrict__ g,
                                             const float* __restrict__ bta,
                                             float* __restrict__ out) {
    int gw = (blockIdx.x * 256 + threadIdx.x) >> 5;
    int lane = threadIdx.x & 31;
    if (gw >= NB*NN) return;
    const float* row = g_Y + (size_t)gw * NC;
    float4 v0 = *(const float4*)(row + lane*8);
    float4 v1 = *(const float4*)(row + lane*8 + 4);
    float s  = (v0.x+v0.y) + (v0.z+v0.w) + (v1.x+v1.y) + (v1.z+v1.w);
    float s2 = v0.x*v0.x + v0.y*v0.y + v0.z*v0.z + v0.w*v0.w
             + v1.x*v1.x + v1.y*v1.y + v1.z*v1.z + v1.w*v1.w;
    #pragma unroll
    for (int o = 16; o; o >>= 1) {
        s  += __shfl_xor_sync(0xffffffffu, s,  o);
        s2 += __shfl_xor_sync(0xffffffffu, s2, o);
    }
    float mu  = s * (1.f/NC);
    float var = s2 * (1.f/NC) - mu * mu;
    float inv = rsqrtf(var + 1e-5f);
    int c = lane * 8;
    float4 g0 = *(const float4*)(g + c),   g1 = *(const float4*)(g + c + 4);
    float4 b0 = *(const float4*)(bta + c), b1 = *(const float4*)(bta + c + 4);
    float4 o0, o1;
    o0.x = (v0.x-mu)*inv*g0.x + b0.x;  o0.y = (v0.y-mu)*inv*g0.y + b0.y;
    o0.z = (v0.z-mu)*inv*g0.z + b0.z;  o0.w = (v0.w-mu)*inv*g0.w + b0.w;
    o1.x = (v1.x-mu)*inv*g1.x + b1.x;  o1.y = (v1.y-mu)*inv*g1.y + b1.y;
    o1.z = (v1.z-mu)*inv*g1.z + b1.z;  o1.w = (v1.w-mu)*inv*g1.w + b1.w;
    *(float4*)(out + (size_t)gw*NC + c)     = o0;
    *(float4*)(out + (size_t)gw*NC + c + 4) = o1;
}

extern "C" void kernel_launch(void* const* d_in, const int* in_sizes, int n_in,
                              void* d_out, int out_size) {
    const float* node = (const float*)d_in[0];
    const float* adj  = (const float*)d_in[1];
    const float* Wlin = (const float*)d_in[2];
    const float* blin = (const float*)d_in[3];
    const float* Wq   = (const float*)d_in[4];
    const float* Wk   = (const float*)d_in[5];
    const float* lng  = (const float*)d_in[6];
    const float* lnb  = (const float*)d_in[7];
    float* out = (float*)d_out;

    const int smem_k2 = (128*72 + 64*72 + 128*72)*2 + 128*4;   // 46,592 B
    const int smem_k4 = 6*64*72*2;                             // 55,296 B
    cudaFuncSetAttribute(k2_att_mma, cudaFuncAttributeMaxDynamicSharedMemorySize, smem_k2);
    cudaFuncSetAttribute(k4_agg_mma, cudaFuncAttributeMaxDynamicSharedMemorySize, smem_k4);

    k0_node<<<(NB*NN*NC)/(256*8), 256>>>(node);
    dim3 g0w(4, 4, 3);
    k0_wt<<<g0w, 256>>>(Wlin, Wq, Wk);

    dim3 g1(NC/128, (NB*NN)/128, 3);
    k1_f16<<<g1, 256>>>(blin);

    dim3 g2(NN/128, NB*NH);                // 256 CTAs, 3/SM -> one wave
    k2_att_mma<<<g2, 256, smem_k2>>>(adj);

    dim3 g3(NN/64, NB*NH);
    k3_xt<<<g3, 256>>>();

    dim3 g4(NN/64, NB*NH);                 // 512 CTAs
    k4_agg_mma<<<g4, 256, smem_k4>>>();

    k5_ln<<<(NB*NN)/8, 256>>>(lng, lnb, out);
}

// round 17
// speedup vs baseline: 1.0197x; 1.0197x over previous
#include <cuda_runtime.h>
#include <cuda_fp16.h>
#include <cstdint>

#define NB 4
#define NN 2048
#define NC 256
#define NH 4
#define HD 64

// ---- scratch (allocation-free) ----
__device__ __half g_nodeh[NB*NN*NC];
__device__ __half g_WT[3*NC*NC];
__device__ __half g_Xh[NB*NN*NC];
__device__ __half g_qh[NB*NN*NC];
__device__ __half g_kh[NB*NN*NC];
__device__ __half g_XT[NB*NH*HD*NN];
__device__ float  g_Y[NB*NN*NC];
__device__ float  g_deg[NB*NH*NN];
__device__ float  g_dis[NB*NH*NN];
__device__ __half g_Wh[(size_t)NB*NH*NN*NN];   // 128MB fp16

__device__ __forceinline__ void mma_f16(float c[4], const uint32_t a[4], const uint32_t b[2]) {
    asm volatile(
        "mma.sync.aligned.m16n8k16.row.col.f32.f16.f16.f32 "
        "{%0,%1,%2,%3}, {%4,%5,%6,%7}, {%8,%9}, {%0,%1,%2,%3};"
        : "+f"(c[0]), "+f"(c[1]), "+f"(c[2]), "+f"(c[3])
        : "r"(a[0]), "r"(a[1]), "r"(a[2]), "r"(a[3]), "r"(b[0]), "r"(b[1]));
}
__device__ __forceinline__ uint32_t smem_cast(const void* p) {
    return (uint32_t)__cvta_generic_to_shared(p);
}
__device__ __forceinline__ void ldsm_x4(uint32_t& r0, uint32_t& r1, uint32_t& r2, uint32_t& r3,
                                        uint32_t addr) {
    asm volatile("ldmatrix.sync.aligned.m8n8.x4.shared.b16 {%0,%1,%2,%3}, [%4];"
        : "=r"(r0), "=r"(r1), "=r"(r2), "=r"(r3) : "r"(addr));
}
__device__ __forceinline__ void cp16(void* s, const void* g) {
    asm volatile("cp.async.cg.shared.global [%0], [%1], 16;"
        :: "r"(smem_cast(s)), "l"(g));
}
#define CP_COMMIT() asm volatile("cp.async.commit_group;" ::: "memory")

__device__ __forceinline__ float sigw(float a, float s) {
    float e = __expf(-0.125f * s);
    return __fdividef(a, 1.f + e);
}

// ============================================================
// K0a: node fp32 -> fp16; also zero g_deg (reuse grid)
// ============================================================
__global__ __launch_bounds__(256) void k0_node(const float* __restrict__ node) {
    int t = blockIdx.x * 256 + threadIdx.x;
    int idx = t * 8;
    float4 v0 = *(const float4*)(node + idx);
    float4 v1 = *(const float4*)(node + idx + 4);
    __half2 h[4];
    h[0] = __float22half2_rn(make_float2(v0.x, v0.y));
    h[1] = __float22half2_rn(make_float2(v0.z, v0.w));
    h[2] = __float22half2_rn(make_float2(v1.x, v1.y));
    h[3] = __float22half2_rn(make_float2(v1.z, v1.w));
    *(uint4*)(g_nodeh + idx) = *(uint4*)h;
    if (t < NB*NH*NN) g_deg[t] = 0.f;
}

// ============================================================
// K0b: weights fp32 [k][n] -> fp16 transposed [n][k]
// ============================================================
__global__ __launch_bounds__(256) void k0_wt(const float* __restrict__ W0,
                                             const float* __restrict__ W1,
                                             const float* __restrict__ W2) {
    __shared__ __half T[64*72];
    const int tid = threadIdx.x;
    const int k0 = blockIdx.x * 64, n0 = blockIdx.y * 64, z = blockIdx.z;
    const float* src = (z == 0) ? W0 : ((z == 1) ? W1 : W2);
    {
        int r = tid >> 2, cp = tid & 3;
        const float* s = src + (size_t)(k0 + r)*NC + n0 + cp*16;
        __half* d = T + r*72 + cp*16;
        #pragma unroll
        for (int u = 0; u < 4; u++) {
            float4 v = *(const float4*)(s + u*4);
            ((__half2*)d)[u*2]   = __float22half2_rn(make_float2(v.x, v.y));
            ((__half2*)d)[u*2+1] = __float22half2_rn(make_float2(v.z, v.w));
        }
    }
    __syncthreads();
    {
        int r = tid >> 2, cp = tid & 3;
        __half* dst = g_WT + (size_t)z*NC*NC + (size_t)(n0 + r)*NC + k0 + cp*16;
        __half tmp[16];
        #pragma unroll
        for (int u = 0; u < 16; u++)
            tmp[u] = T[(cp*16 + u)*72 + r];
        *(uint4*)(dst)     = *(uint4*)(tmp);
        *(uint4*)(dst + 8) = *(uint4*)(tmp + 8);
    }
}

// ============================================================
// K1 (mma fp16): out = lrelu(node @ W (+bias)), z selects W
// ============================================================
__global__ __launch_bounds__(256) void k1_f16(const float* __restrict__ bias) {
    __shared__ __half As[128*72];
    __shared__ __half Bs[128*72];
    const int tid = threadIdx.x;
    const int wid = tid >> 5, lid = tid & 31;
    const int grp = lid >> 2, tg = lid & 3;
    const int wm = wid >> 2, wn = wid & 3;
    const int z = blockIdx.z;
    const int M0 = blockIdx.y * 128, N0 = blockIdx.x * 128;
    __half* outp = (z == 0) ? g_Xh : ((z == 1) ? g_qh : g_kh);
    const __half* Asrc = g_nodeh + (size_t)M0*NC;
    const __half* Bsrc = g_WT + (size_t)z*NC*NC + (size_t)N0*NC;
    const int srow = tid >> 1, spart = tid & 1;
    const int a_row = lid & 15, a_koff = (lid >> 4) * 8;
    const int b_row = ((lid >> 4) & 1) * 8 + (lid & 7), b_koff = ((lid >> 3) & 1) * 8;

    float acc[4][4][4] = {};
    for (int kc = 0; kc < 4; kc++) {
        const int k0 = kc * 64;
        __syncthreads();
        {
            const uint4* g = (const uint4*)(Asrc + (size_t)srow*NC + k0 + spart*32);
            uint4* s = (uint4*)(As + srow*72 + spart*32);
            s[0]=g[0]; s[1]=g[1]; s[2]=g[2]; s[3]=g[3];
            const uint4* gb = (const uint4*)(Bsrc + (size_t)srow*NC + k0 + spart*32);
            uint4* sb = (uint4*)(Bs + srow*72 + spart*32);
            sb[0]=gb[0]; sb[1]=gb[1]; sb[2]=gb[2]; sb[3]=gb[3];
        }
        __syncthreads();
        #pragma unroll
        for (int kk = 0; kk < 4; kk++) {
            uint32_t a[4][4], bf[4][2];
            #pragma unroll
            for (int i = 0; i < 4; i++) {
                uint32_t ad = smem_cast(As + (wm*64 + i*16 + a_row)*72 + kk*16 + a_koff);
                ldsm_x4(a[i][0], a[i][1], a[i][2], a[i][3], ad);
            }
            #pragma unroll
            for (int jj = 0; jj < 2; jj++) {
                uint32_t bd = smem_cast(Bs + (wn*32 + jj*16 + b_row)*72 + kk*16 + b_koff);
                ldsm_x4(bf[2*jj][0], bf[2*jj][1], bf[2*jj+1][0], bf[2*jj+1][1], bd);
            }
            #pragma unroll
            for (int i = 0; i < 4; i++)
                #pragma unroll
                for (int j = 0; j < 4; j++)
                    mma_f16(acc[i][j], a[i], bf[j]);
        }
    }
    #pragma unroll
    for (int i = 0; i < 4; i++)
        #pragma unroll
        for (int u = 0; u < 2; u++) {
            int row = M0 + wm*64 + i*16 + grp + u*8;
            #pragma unroll
            for (int j = 0; j < 4; j++) {
                int col = N0 + wn*32 + j*8 + tg*2;
                float v0 = acc[i][j][u*2], v1 = acc[i][j][u*2+1];
                if (z == 0) { v0 += bias[col]; v1 += bias[col+1]; }
                v0 = (v0 >= 0.f) ? v0 : 0.01f*v0;
                v1 = (v1 >= 0.f) ? v1 : 0.01f*v1;
                *(__half2*)(outp + (size_t)row*NC + col) =
                    __float22half2_rn(make_float2(v0, v1));
            }
        }
}

// ============================================================
// K2 (mma fp16, 128x64 y-tiles, y-range split over blockIdx.z):
// W = adj*sigmoid(q.k/8) -> fp16, partial deg -> atomicAdd(g_deg)
// ============================================================
#define K2_SPLIT 2
__global__ __launch_bounds__(256, 3) void k2_att_mma(const float* __restrict__ adj) {
    extern __shared__ char smraw[];
    __half* qs  = (__half*)smraw;                 // 128*72 halves
    __half* ks  = qs + 128*72;                    // 64*72 halves
    __half* Sh  = ks + 64*72;                     // 128*72 halves
    float*  red = (float*)(Sh + 128*72);          // 128 floats
    const int tid = threadIdx.x;
    const int wid = tid >> 5, lid = tid & 31;
    const int grp = lid >> 2, tg = lid & 3;
    const int wm = wid >> 1, wn = wid & 1;
    const int bh = blockIdx.y;
    const int b = bh >> 2, h = bh & 3;
    const int x0 = blockIdx.x * 128;
    const int yh = blockIdx.z;
    const int qrow = tid >> 1, qpart = tid & 1;
    const int krow = tid >> 2, kpart = tid & 3;
    const int rl8 = lid >> 3, rl = lid & 7;

    const int a_row = lid & 15, a_koff = (lid >> 4) * 8;
    const int b_row = ((lid >> 4) & 1) * 8 + (lid & 7), b_koff = ((lid >> 3) & 1) * 8;

    {   // stage q once
        const uint4* g = (const uint4*)(g_qh + ((size_t)(b*NN + x0 + qrow))*NC + h*HD + qpart*32);
        uint4* s = (uint4*)(qs + qrow*72 + qpart*32);
        s[0]=g[0]; s[1]=g[1]; s[2]=g[2]; s[3]=g[3];
    }
    if (tid < 128) red[tid] = 0.f;

    const __half* ksrc  = g_kh + (size_t)b*NN*NC + h*HD;
    const float*  abase = adj + (size_t)b*NN*NN;
    __half* wbase = g_Wh + (size_t)bh*NN*NN;

    const int yt0 = yh * (NN/64/K2_SPLIT), yt1 = yt0 + NN/64/K2_SPLIT;
    for (int yt = yt0; yt < yt1; yt++) {
        const int y0 = yt * 64;
        {   // stage k tile: 64 rows x 64 halves
            const uint4* g = (const uint4*)(ksrc + (size_t)(y0 + krow)*NC + kpart*16);
            uint4* s = (uint4*)(ks + krow*72 + kpart*16);
            s[0]=g[0]; s[1]=g[1];
        }
        __syncthreads();
        float acc[2][4][4] = {};
        #pragma unroll
        for (int kk = 0; kk < 4; kk++) {
            uint32_t a[2][4], bf[4][2];
            #pragma unroll
            for (int i = 0; i < 2; i++) {
                uint32_t ad = smem_cast(qs + (wm*32 + i*16 + a_row)*72 + kk*16 + a_koff);
                ldsm_x4(a[i][0], a[i][1], a[i][2], a[i][3], ad);
            }
            #pragma unroll
            for (int jj = 0; jj < 2; jj++) {
                uint32_t bd = smem_cast(ks + (wn*32 + jj*16 + b_row)*72 + kk*16 + b_koff);
                ldsm_x4(bf[2*jj][0], bf[2*jj][1], bf[2*jj+1][0], bf[2*jj+1][1], bd);
            }
            #pragma unroll
            for (int i = 0; i < 2; i++)
                #pragma unroll
                for (int j = 0; j < 4; j++)
                    mma_f16(acc[i][j], a[i], bf[j]);
        }
        #pragma unroll
        for (int i = 0; i < 2; i++) {
            int xr = wm*32 + i*16 + grp;
            #pragma unroll
            for (int j = 0; j < 4; j++) {
                int col = wn*32 + j*8 + 2*tg;
                *(__half2*)(Sh + xr*72 + col) =
                    __float22half2_rn(make_float2(acc[i][j][0], acc[i][j][1]));
                *(__half2*)(Sh + (xr+8)*72 + col) =
                    __float22half2_rn(make_float2(acc[i][j][2], acc[i][j][3]));
            }
        }
        __syncthreads();
        #pragma unroll
        for (int p = 0; p < 4; p++) {
            int xr = p*32 + wid*4 + rl8;
            const __half* Srow = Sh + xr*72;
            const float* arow = abase + (size_t)(x0 + xr)*NN + y0;
            __half* wrow = wbase + (size_t)(x0 + xr)*NN + y0;
            float4 av[2];
            uint2 svh[2];
            #pragma unroll
            for (int c = 0; c < 2; c++) av[c] = *(const float4*)(arow + c*32 + rl*4);
            #pragma unroll
            for (int c = 0; c < 2; c++) svh[c] = *(const uint2*)(Srow + c*32 + rl*4);
            float lsum = 0.f;
            #pragma unroll
            for (int c = 0; c < 2; c++) {
                float2 s01 = __half22float2(*(__half2*)&svh[c].x);
                float2 s23 = __half22float2(*(__half2*)&svh[c].y);
                float w0 = sigw(av[c].x, s01.x);
                float w1 = sigw(av[c].y, s01.y);
                float w2 = sigw(av[c].z, s23.x);
                float w3 = sigw(av[c].w, s23.y);
                __half2 h0 = __float22half2_rn(make_float2(w0, w1));
                __half2 h1 = __float22half2_rn(make_float2(w2, w3));
                uint2 st = make_uint2(*(uint32_t*)&h0, *(uint32_t*)&h1);
                *(uint2*)(wrow + c*32 + rl*4) = st;
                lsum += (w0 + w1) + (w2 + w3);
            }
            lsum += __shfl_xor_sync(0xffffffffu, lsum, 1);
            lsum += __shfl_xor_sync(0xffffffffu, lsum, 2);
            lsum += __shfl_xor_sync(0xffffffffu, lsum, 4);
            if (rl == 0) red[xr] += lsum;
        }
        __syncthreads();
    }
    if (tid < 128)
        atomicAdd(&g_deg[bh*NN + x0 + tid], red[tid]);
}

// ============================================================
// K2b: dis = rsqrt(deg)
// ============================================================
__global__ __launch_bounds__(256) void k2b_dis() {
    int t = blockIdx.x * 256 + threadIdx.x;
    float v = g_deg[t];
    g_dis[t] = (v > 0.f) ? rsqrtf(v) : 0.f;
}

// ============================================================
// K3x: g_XT[bh][d][y] = fp16(dis_y * X[b,y,h*64+d])
// ============================================================
__global__ __launch_bounds__(256) void k3_xt() {
    __shared__ __half T[64*72];
    const int tid = threadIdx.x;
    const int yt = blockIdx.x, bh = blockIdx.y;
    const int b = bh >> 2, h = bh & 3;
    const int y0 = yt * 64;
    {
        int yr = tid >> 2, cp = tid & 3;
        float dy = g_dis[bh*NN + y0 + yr];
        const __half* src = g_Xh + ((size_t)(b*NN + y0 + yr))*NC + h*HD + cp*16;
        __half* dst = T + yr*72 + cp*16;
        #pragma unroll
        for (int u = 0; u < 8; u++) {
            float2 f = __half22float2(((const __half2*)src)[u]);
            ((__half2*)dst)[u] = __float22half2_rn(make_float2(f.x*dy, f.y*dy));
        }
    }
    __syncthreads();
    {
        int dr = tid >> 2, cp = tid & 3;
        __half* dst = g_XT + ((size_t)bh*HD + dr)*NN + y0 + cp*16;
        __half tmp[16];
        #pragma unroll
        for (int u = 0; u < 16; u++)
            tmp[u] = T[(cp*16 + u)*72 + dr];
        *(uint4*)(dst)     = *(uint4*)(tmp);
        *(uint4*)(dst + 8) = *(uint4*)(tmp + 8);
    }
}

// ============================================================
// K4 (mma fp16, 64x64 tile, grid 512, 3-stage cp.async)
// ============================================================
#define K4_ITERS (NN/64)
__global__ __launch_bounds__(256, 4) void k4_agg_mma() {
    extern __shared__ char smraw[];
    __half* Ws = (__half*)smraw;          // 3 x 64*72
    __half* Xs = Ws + 3*64*72;            // 3 x 64*72
    const int tid = threadIdx.x;
    const int wid = tid >> 5, lid = tid & 31;
    const int grp = lid >> 2, tg = lid & 3;
    const int wm = wid >> 2, wn = wid & 3;
    const int bh = blockIdx.y;
    const int b = bh >> 2, h = bh & 3;
    const int x0 = blockIdx.x * 64;
    const __half* wsrc  = g_Wh + (size_t)bh*NN*NN + (size_t)x0*NN;
    const __half* xtsrc = g_XT + (size_t)bh*HD*NN;
    const float*  disb  = g_dis + bh*NN;
    const int row4 = tid >> 2, part4 = tid & 3;
    const int a_row = lid & 15, a_koff = (lid >> 4) * 8;
    const int b_row = ((lid >> 4) & 1) * 8 + (lid & 7), b_koff = ((lid >> 3) & 1) * 8;

    auto issue = [&](int it) {
        int st = it % 3;
        int y0 = it * 64;
        const __half* gw = wsrc + (size_t)row4*NN + y0 + part4*16;
        __half* sw = Ws + st*64*72 + row4*72 + part4*16;
        cp16(sw, gw); cp16(sw + 8, gw + 8);
        const __half* gx = xtsrc + (size_t)row4*NN + y0 + part4*16;
        __half* sx = Xs + st*64*72 + row4*72 + part4*16;
        cp16(sx, gx); cp16(sx + 8, gx + 8);
        CP_COMMIT();
    };

    issue(0);
    issue(1);
    float acc[2][2][4] = {};
    for (int it = 0; it < K4_ITERS; it++) {
        if (it + 1 < K4_ITERS) {
            asm volatile("cp.async.wait_group 1;" ::: "memory");
        } else {
            asm volatile("cp.async.wait_group 0;" ::: "memory");
        }
        __syncthreads();
        if (it + 2 < K4_ITERS) issue(it + 2);
        __half* Wb = Ws + (it % 3) * 64*72;
        __half* Xb = Xs + (it % 3) * 64*72;
        #pragma unroll
        for (int kk = 0; kk < 4; kk++) {
            uint32_t a[2][4], bf[2][2];
            #pragma unroll
            for (int i = 0; i < 2; i++) {
                uint32_t ad = smem_cast(Wb + (wm*32 + i*16 + a_row)*72 + kk*16 + a_koff);
                ldsm_x4(a[i][0], a[i][1], a[i][2], a[i][3], ad);
            }
            {
                uint32_t bd = smem_cast(Xb + (wn*16 + b_row)*72 + kk*16 + b_koff);
                ldsm_x4(bf[0][0], bf[0][1], bf[1][0], bf[1][1], bd);
            }
            #pragma unroll
            for (int i = 0; i < 2; i++)
                #pragma unroll
                for (int j = 0; j < 2; j++)
                    mma_f16(acc[i][j], a[i], bf[j]);
        }
    }
    #pragma unroll
    for (int i = 0; i < 2; i++) {
        #pragma unroll
        for (int u = 0; u < 2; u++) {
            int x = x0 + wm*32 + i*16 + grp + u*8;
            float dx = disb[x];
            float* dst = g_Y + (size_t)(b*NN + x)*NC + h*HD + wn*16 + tg*2;
            #pragma unroll
            for (int j = 0; j < 2; j++)
                *(float2*)(dst + j*8) = make_float2(acc[i][j][u*2]*dx, acc[i][j][u*2+1]*dx);
        }
    }
}

// ============================================================
// K5: LayerNorm over last dim (256), warp per row
// ============================================================
__global__ __launch_bounds__(256) void k5_ln(const float* __restrict__ g,
                                             const float* __restrict__ bta,
                                             float* __restrict__ out) {
    int gw = (blockIdx.x * 256 + threadIdx.x) >> 5;
    int lane = threadIdx.x & 31;
    if (gw >= NB*NN) return;
    const float* row = g_Y + (size_t)gw * NC;
    float4 v0 = *(const float4*)(row + lane*8);
    float4 v1 = *(const float4*)(row + lane*8 + 4);
    float s  = (v0.x+v0.y) + (v0.z+v0.w) + (v1.x+v1.y) + (v1.z+v1.w);
    float s2 = v0.x*v0.x + v0.y*v0.y + v0.z*v0.z + v0.w*v0.w
             + v1.x*v1.x + v1.y*v1.y + v1.z*v1.z + v1.w*v1.w;
    #pragma unroll
    for (int o = 16; o; o >>= 1) {
        s  += __shfl_xor_sync(0xffffffffu, s,  o);
        s2 += __shfl_xor_sync(0xffffffffu, s2, o);
    }
    float mu  = s * (1.f/NC);
    float var = s2 * (1.f/NC) - mu * mu;
    float inv = rsqrtf(var + 1e-5f);
    int c = lane * 8;
    float4 g0 = *(const float4*)(g + c),   g1 = *(const float4*)(g + c + 4);
    float4 b0 = *(const float4*)(bta + c), b1 = *(const float4*)(bta + c + 4);
    float4 o0, o1;
    o0.x = (v0.x-mu)*inv*g0.x + b0.x;  o0.y = (v0.y-mu)*inv*g0.y + b0.y;
    o0.z = (v0.z-mu)*inv*g0.z + b0.z;  o0.w = (v0.w-mu)*inv*g0.w + b0.w;
    o1.x = (v1.x-mu)*inv*g1.x + b1.x;  o1.y = (v1.y-mu)*inv*g1.y + b1.y;
    o1.z = (v1.z-mu)*inv*g1.z + b1.z;  o1.w = (v1.w-mu)*inv*g1.w + b1.w;
    *(float4*)(out + (size_t)gw*NC + c)     = o0;
    *(float4*)(out + (size_t)gw*NC + c + 4) = o1;
}

extern "C" void kernel_launch(void* const* d_in, const int* in_sizes, int n_in,
                              void* d_out, int out_size) {
    const float* node = (const float*)d_in[0];
    const float* adj  = (const float*)d_in[1];
    const float* Wlin = (const float*)d_in[2];
    const float* blin = (const float*)d_in[3];
    const float* Wq   = (const float*)d_in[4];
    const float* Wk   = (const float*)d_in[5];
    const float* lng  = (const float*)d_in[6];
    const float* lnb  = (const float*)d_in[7];
    float* out = (float*)d_out;

    const int smem_k2 = (128*72 + 64*72 + 128*72)*2 + 128*4;   // 46,592 B
    const int smem_k4 = 6*64*72*2;                             // 55,296 B
    cudaFuncSetAttribute(k2_att_mma, cudaFuncAttributeMaxDynamicSharedMemorySize, smem_k2);
    cudaFuncSetAttribute(k4_agg_mma, cudaFuncAttributeMaxDynamicSharedMemorySize, smem_k4);

    k0_node<<<(NB*NN*NC)/(256*8), 256>>>(node);
    dim3 g0w(4, 4, 3);
    k0_wt<<<g0w, 256>>>(Wlin, Wq, Wk);

    dim3 g1(NC/128, (NB*NN)/128, 3);
    k1_f16<<<g1, 256>>>(blin);

    dim3 g2(NN/128, NB*NH, K2_SPLIT);      // 512 CTAs, 3/SM
    k2_att_mma<<<g2, 256, smem_k2>>>(adj);

    k2b_dis<<<(NB*NH*NN)/256, 256>>>();

    dim3 g3(NN/64, NB*NH);
    k3_xt<<<g3, 256>>>();

    dim3 g4(NN/64, NB*NH);                 // 512 CTAs
    k4_agg_mma<<<g4, 256, smem_k4>>>();

    k5_ln<<<(NB*NN)/8, 256>>>(lng, lnb, out);
}